// round 17
// baseline (speedup 1.0000x reference)
#include <cuda_runtime.h>
#include <cstdint>

typedef unsigned long long u64;
typedef unsigned int u32;

#define G_DIM 2048
#define T_DIM 16
#define B_DIM 256
#define P_DIM 64

// Device-global scratch (no allocations allowed)
__device__ u64  g_pv[B_DIM];
__device__ int4 g_T[3 * 17 * 17];   // (1+w^{k+1})^a (1-w^{k+1})^b, a+b<=16

// ---------------------------------------------------------------------------
// Ring ops in basis (1, w, w^2, w^3), w^4 = -1.
// ---------------------------------------------------------------------------
__device__ __forceinline__ void ringmul(int* z, const int* x, const int* y) {
    z[0] = x[0]*y[0] - x[1]*y[3] - x[2]*y[2] - x[3]*y[1];
    z[1] = x[0]*y[1] + x[1]*y[0] - x[2]*y[3] - x[3]*y[2];
    z[2] = x[0]*y[2] + x[1]*y[1] + x[2]*y[0] - x[3]*y[3];
    z[3] = x[0]*y[3] + x[1]*y[2] + x[2]*y[1] + x[3]*y[0];
}
__device__ __forceinline__ void ringcpy(int* d, const int* s) {
    d[0] = s[0]; d[1] = s[1]; d[2] = s[2]; d[3] = s[3];
}
__device__ __forceinline__ void ringpow(int* acc, const int* f, int n) {
    int base[4], tmp[4];
    acc[0] = 1; acc[1] = 0; acc[2] = 0; acc[3] = 0;
    ringcpy(base, f);
    while (n) {
        if (n & 1) { ringmul(tmp, acc, base); ringcpy(acc, tmp); }
        n >>= 1;
        if (n) { ringmul(tmp, base, base); ringcpy(base, tmp); }
    }
}
__device__ __forceinline__ int clamp_cnt(int c) {
    return c < 0 ? 0 : (c > T_DIM ? T_DIM : c);
}

// ---------------------------------------------------------------------------
// Init: 12 blocks. Blocks 0..3 build g_T (867 entries, one per thread).
// Blocks 4..11 pack param_vals (8 warps x 4 rows each = 32 rows/block).
// ---------------------------------------------------------------------------
__global__ void init_kernel(const int* __restrict__ param_vals) {
    if (blockIdx.x < 4) {
        int e = blockIdx.x * 256 + threadIdx.x;
        if (e < 3 * 289) {
            int k = e / 289, r = e % 289, a = r / 17, b = r % 17;
            int4 o;
            if (a + b > 16) {
                o = make_int4(0, 0, 0, 0);
            } else {
                int kk = k + 1;
                int fp[4] = {1, 0, 0, 0}; fp[kk] = 1;
                int fm[4] = {1, 0, 0, 0}; fm[kk] = -1;
                int pa[4], pb[4], acc[4];
                ringpow(pa, fp, a);
                ringpow(pb, fm, b);
                ringmul(acc, pa, pb);
                o = make_int4(acc[0], acc[1], acc[2], acc[3]);
            }
            g_T[e] = o;
        }
    } else {
        int warp = threadIdx.x >> 5, lane = threadIdx.x & 31;
        int row0 = ((blockIdx.x - 4) * 8 + warp) * 4;
        int a[4], b[4];
        #pragma unroll
        for (int r = 0; r < 4; r++) {
            const int* p = param_vals + (size_t)(row0 + r) * P_DIM;
            a[r] = p[lane]; b[r] = p[lane + 32];
        }
        #pragma unroll
        for (int r = 0; r < 4; r++) {
            u32 lo = __ballot_sync(0xffffffffu, a[r] & 1);
            u32 hi = __ballot_sync(0xffffffffu, b[r] & 1);
            if (lane == 0) g_pv[row0 + r] = ((u64)hi << 32) | (u64)lo;
        }
    }
}

// ---------------------------------------------------------------------------
// Main: 1024 blocks x 256 threads. Block = 2 g's x all 256 b's; thread = one
// b x both g's. Fused prologue (ONE barrier):
//   all 8 warps: ballot-pack 4 of the 32 param rows each into s_term.{x,y}
//   warps 0,1:  meta for g0+warp (s_pack, m0, cnt) + per-term pw
//   warps 2..7: (gi,kk): re-ballot class mask, copy row entries b=0..m from
//               g_T (class-1 rows pre-scaled by 2^m0).
// Parity: 4x4 chunked with NESTED UNIFORM early-exit on cnt (valid terms are
// a prefix; E[chunks] = 2.5 of 4). Chains alternate cpA/cpB per chunk.
// Epilogue: R = A*C (16 IMAD), Z = R*B with class-2 B in Z[i] (8 IMAD);
// zero-flag via float select. Stores staged in smem, transposed to
// 32B-contiguous (b, g-pair) chunks.
// Output float32 (B, G, 4) in reference basis (1,w,w^2,w^7): c3 = -z3.
// ---------------------------------------------------------------------------
__global__ void __launch_bounds__(256, 6)
nodephases_main_kernel(const int* __restrict__ params,
                       const int* __restrict__ phases,
                       const int* __restrict__ counts,
                       float* __restrict__ out) {
    const int g0   = blockIdx.x * 2;
    const int tid  = threadIdx.x;
    const int lane = tid & 31;
    const int warp = tid >> 5;

    __shared__ int4   s_term[2][T_DIM];     // x=lo, y=hi, z=pw
    __shared__ int4   s_meta[2];            // x=s_pack, y=m0, z=cnt
    __shared__ int4   s_rows[2][3][17];
    __shared__ float4 s_out[B_DIM][2];

    // ---- pack: warp w -> rows w*4 .. w*4+3 (row = gi*16 + t) ----
    {
        const int row0 = warp * 4;
        const int* basep = params + ((size_t)g0 * T_DIM + row0) * P_DIM;
        int a[4], b[4];
        #pragma unroll
        for (int r = 0; r < 4; r++) {
            a[r] = basep[r * P_DIM + lane];
            b[r] = basep[r * P_DIM + 32 + lane];
        }
        #pragma unroll
        for (int r = 0; r < 4; r++) {
            u32 lo = __ballot_sync(0xffffffffu, a[r] & 1);
            u32 hi = __ballot_sync(0xffffffffu, b[r] & 1);
            if (lane == 0) {
                int row = row0 + r;
                s_term[row >> 4][row & 15].x = (int)lo;
                s_term[row >> 4][row & 15].y = (int)hi;
            }
        }
    }

    // ---- role work (no cross-warp dependencies; one barrier after) ----
    if (warp < 2) {
        // meta + pw for g = g0 + warp
        const int gi = warp;
        const int g  = g0 + gi;
        int c = clamp_cnt(counts[g]);
        u32 vm = (c >= 16) ? 0xFFFFu : ((1u << c) - 1u);
        int p  = (lane < 16) ? (phases[g * T_DIM + lane] & 7) : 0;
        int k  = p & 3;
        int sg = (p >> 2) & 1;
        u32 b0m = __ballot_sync(0xffffffffu, k == 0) & vm;
        u32 b1m = __ballot_sync(0xffffffffu, k == 1) & vm;
        u32 b2m = __ballot_sync(0xffffffffu, k == 2) & vm;
        u32 b3m = __ballot_sync(0xffffffffu, k == 3) & vm;
        u32 sgm = __ballot_sync(0xffffffffu, sg == 1) & vm;
        if (lane < 16) {
            int valid = (vm >> lane) & 1;
            s_term[gi][lane].z = valid ? (sg ? -(1 << (8 * k)) : (1 << (8 * k))) : 0;
        }
        if (lane == 0) {
            int s0 = __popc(b0m & sgm), s1 = __popc(b1m & sgm),
                s2 = __popc(b2m & sgm), s3 = __popc(b3m & sgm);
            s_meta[gi] = make_int4(s0 | (s1 << 8) | (s2 << 16) | (s3 << 24),
                                   __popc(b0m), c, 0);
        }
    } else {
        // rows: warp w covers (gi = (w-2)/3, class kk = (w-2)%3 + 1)
        const int w  = warp - 2;
        const int gi = w / 3;
        const int kk = w % 3 + 1;
        const int g  = g0 + gi;
        int c = clamp_cnt(counts[g]);
        u32 vm = (c >= 16) ? 0xFFFFu : ((1u << c) - 1u);
        int p  = (lane < 16) ? (phases[g * T_DIM + lane] & 7) : 0;
        u32 km  = __ballot_sync(0xffffffffu, ((p & 3) == kk) && (lane < 16)) & vm;
        u32 b0m = __ballot_sync(0xffffffffu, ((p & 3) == 0)  && (lane < 16)) & vm;
        int m  = __popc(km);
        int m0 = __popc(b0m);
        if (lane <= m) {
            int4 e = __ldg(&g_T[(kk - 1) * 289 + (m - lane) * 17 + lane]);
            if (kk == 1) { e.x <<= m0; e.y <<= m0; e.z <<= m0; e.w <<= m0; }
            s_rows[gi][kk - 1][lane] = e;
        }
    }
    __syncthreads();

    // ---- compute: one b, two g's ----
    const u64 v = g_pv[tid];
    const u32 vlo = (u32)v, vhi = (u32)(v >> 32);

    #pragma unroll
    for (int gi = 0; gi < 2; gi++) {
        const int4 meta = s_meta[gi];
        const int  cnt  = meta.z;

        int cpA = meta.x;
        int cpB = 0x10101010;

        // chunked parity with nested uniform early-exit (valid terms = prefix)
        #pragma unroll
        for (int tt = 0; tt < 4; tt++) {
            int4 tw = s_term[gi][tt];
            u32 x = ((u32)tw.x & vlo) ^ ((u32)tw.y & vhi);
            cpA += (int)(__popc(x) & 1u) * tw.z;
        }
        if (cnt > 4) {
            #pragma unroll
            for (int tt = 4; tt < 8; tt++) {
                int4 tw = s_term[gi][tt];
                u32 x = ((u32)tw.x & vlo) ^ ((u32)tw.y & vhi);
                cpB += (int)(__popc(x) & 1u) * tw.z;
            }
            if (cnt > 8) {
                #pragma unroll
                for (int tt = 8; tt < 12; tt++) {
                    int4 tw = s_term[gi][tt];
                    u32 x = ((u32)tw.x & vlo) ^ ((u32)tw.y & vhi);
                    cpA += (int)(__popc(x) & 1u) * tw.z;
                }
                if (cnt > 12) {
                    #pragma unroll
                    for (int tt = 12; tt < 16; tt++) {
                        int4 tw = s_term[gi][tt];
                        u32 x = ((u32)tw.x & vlo) ^ ((u32)tw.y & vhi);
                        cpB += (int)(__popc(x) & 1u) * tw.z;
                    }
                }
            }
        }
        int cp = cpA + cpB - 0x10101010;

        int b0 = cp & 255;
        int b1 = (cp >> 8) & 255;
        int b2 = (cp >> 16) & 255;
        int b3 = (cp >> 24) & 255;

        int4 A  = s_rows[gi][0][b1];   // class 1, pre-scaled by 2^m0
        int4 Bc = s_rows[gi][1][b2];   // class 2: only .x, .z nonzero
        int4 C  = s_rows[gi][2][b3];   // class 3

        int r0 = A.x*C.x - A.y*C.w - A.z*C.z - A.w*C.y;
        int r1 = A.x*C.y + A.y*C.x - A.z*C.w - A.w*C.z;
        int r2 = A.x*C.z + A.y*C.y + A.z*C.x - A.w*C.w;
        int r3 = A.x*C.w + A.y*C.z + A.z*C.y + A.w*C.x;

        int z0 = r0*Bc.x - r2*Bc.z;
        int z1 = r1*Bc.x - r3*Bc.z;
        int z2 = r2*Bc.x + r0*Bc.z;
        int z3 = r3*Bc.x + r1*Bc.z;

        bool nz = (b0 == 0);
        float f0 = nz ? (float)z0 : 0.0f;
        float f1 = nz ? (float)z1 : 0.0f;
        float f2 = nz ? (float)z2 : 0.0f;
        float f3 = nz ? (float)(-z3) : 0.0f;   // basis: c3_ref = -z3

        s_out[tid][gi] = make_float4(f0, f1, f2, f3);
    }
    __syncthreads();

    // ---- store phase: lane-consecutive (b, gs) -> 32B contiguous chunks ----
    float4* out4 = (float4*)out;
    #pragma unroll
    for (int r = 0; r < 2; r++) {
        int idx = tid + r * 256;
        int b  = idx >> 1;
        int gs = idx & 1;
        out4[(size_t)b * G_DIM + g0 + gs] = s_out[b][gs];
    }
}

// ---------------------------------------------------------------------------
// Launch. Inputs identified BY SIZE (ordering-proof):
//   phases 32768 | params 2097152 | counts 2048 | param_vals 16384 | opp 32
// ---------------------------------------------------------------------------
extern "C" void kernel_launch(void* const* d_in, const int* in_sizes, int n_in,
                              void* d_out, int out_size) {
    const int* phases = nullptr;
    const int* params = nullptr;
    const int* counts = nullptr;
    const int* param_vals = nullptr;

    for (int i = 0; i < n_in; i++) {
        switch (in_sizes[i]) {
            case G_DIM * T_DIM:         phases     = (const int*)d_in[i]; break;
            case G_DIM * T_DIM * P_DIM: params     = (const int*)d_in[i]; break;
            case G_DIM:                 counts     = (const int*)d_in[i]; break;
            case B_DIM * P_DIM:         param_vals = (const int*)d_in[i]; break;
            default: break;  // one_plus_phases (32 floats) — unused
        }
    }

    init_kernel<<<12, 256>>>(param_vals);
    nodephases_main_kernel<<<G_DIM / 2, 256>>>(params, phases, counts,
                                               (float*)d_out);
}